// round 1
// baseline (speedup 1.0000x reference)
#include <cuda_runtime.h>
#include <math.h>

// Problem constants
#define NB 4
#define NH 8
#define SQ 2048
#define DM 768
#define DH 96
// derived
#define M_TOT (NB * SQ)          // 8192
#define QKV_ELEMS (NB * NH * SQ * DH)  // 6291456

// Scratch (allocation-free rule: static device globals)
__device__ float g_Q[QKV_ELEMS];
__device__ float g_K[QKV_ELEMS];
__device__ float g_V[QKV_ELEMS];
__device__ float g_O[QKV_ELEMS];

// ---------------------------------------------------------------------------
// Kernel 1: QKV projections.
// out[b][h][s][k] = sum_d X[b][s][d] * W[h][d][k] + bias[h][k]
// GEMM view: A = X [8192 x 768], B = W with column c = h*96+k, C [8192 x 768].
// Tile 64x64, K-chunk 16, 256 threads, 4x4 register microtile.
// ---------------------------------------------------------------------------
__global__ __launch_bounds__(256) void qkv_kernel(
    const float* __restrict__ Xq, const float* __restrict__ Xk, const float* __restrict__ Xv,
    const float* __restrict__ Wq, const float* __restrict__ Wk, const float* __restrict__ Wv,
    const float* __restrict__ bq, const float* __restrict__ bk, const float* __restrict__ bv)
{
    const int which = blockIdx.z;
    const float* __restrict__ X    = (which == 0) ? Xq : (which == 1) ? Xk : Xv;
    const float* __restrict__ W    = (which == 0) ? Wq : (which == 1) ? Wk : Wv;
    const float* __restrict__ bias = (which == 0) ? bq : (which == 1) ? bk : bv;
    float* __restrict__ out        = (which == 0) ? g_Q : (which == 1) ? g_K : g_V;

    __shared__ float As[16][68];   // [k][m], padded, float4-aligned rows
    __shared__ float Bs[16][68];   // [k][c]

    const int m0 = blockIdx.y * 64;
    const int c0 = blockIdx.x * 64;
    const int tid = threadIdx.x;
    const int tx = tid & 15;
    const int ty = tid >> 4;

    float acc[4][4] = {};

    for (int k0 = 0; k0 < DM; k0 += 16) {
        // Load A tile 64x16 (4 elems/thread)
        #pragma unroll
        for (int i = 0; i < 4; i++) {
            int idx = tid + i * 256;
            int m = idx >> 4, k = idx & 15;
            As[k][m] = X[(m0 + m) * DM + k0 + k];
        }
        // Load B tile 16x64 (4 elems/thread)
        #pragma unroll
        for (int i = 0; i < 4; i++) {
            int idx = tid + i * 256;
            int c = idx & 63, k = idx >> 6;
            int cc = c0 + c;
            int h = cc / DH, kk = cc % DH;
            Bs[k][c] = W[h * (DM * DH) + (k0 + k) * DH + kk];
        }
        __syncthreads();

        #pragma unroll
        for (int k = 0; k < 16; k++) {
            float4 a = *(const float4*)&As[k][ty * 4];
            float4 b = *(const float4*)&Bs[k][tx * 4];
            float av[4] = {a.x, a.y, a.z, a.w};
            float bv4[4] = {b.x, b.y, b.z, b.w};
            #pragma unroll
            for (int i = 0; i < 4; i++)
                #pragma unroll
                for (int j = 0; j < 4; j++)
                    acc[i][j] += av[i] * bv4[j];
        }
        __syncthreads();
    }

    // Store with bias, scatter into [B,H,S,DH] layout
    #pragma unroll
    for (int i = 0; i < 4; i++) {
        int m = m0 + ty * 4 + i;
        int b = m >> 11;          // /2048
        int s = m & 2047;
        #pragma unroll
        for (int j = 0; j < 4; j++) {
            int c = c0 + tx * 4 + j;
            int h = c / DH, kk = c % DH;
            out[(((b * NH) + h) * SQ + s) * DH + kk] = acc[i][j] + bias[c];
        }
    }
}

// ---------------------------------------------------------------------------
// Kernel 2: flash attention, fp32.
// One block per (b*h, q-tile of 64). 256 threads (16x16), Bc = 64.
// Shared: Qs[64][97], Ks[64][97], Vs[64][97], P[64][65]  -> 91136 bytes.
// ---------------------------------------------------------------------------
#define QS_STRIDE 97
#define PS_STRIDE 65
#define ATTN_SMEM ((3 * 64 * QS_STRIDE + 64 * PS_STRIDE) * 4)

__global__ __launch_bounds__(256) void attn_kernel()
{
    extern __shared__ float sm[];
    float* Qs = sm;                       // [64][97]
    float* Ks = Qs + 64 * QS_STRIDE;      // [64][97]
    float* Vs = Ks + 64 * QS_STRIDE;      // [64][97]
    float* Ps = Vs + 64 * QS_STRIDE;      // [64][65]

    const int bh = blockIdx.y;            // 0..31
    const int q0 = blockIdx.x * 64;
    const int tid = threadIdx.x;
    const int tx = tid & 15;
    const int ty = tid >> 4;
    const float scale = rsqrtf((float)DH);

    const float* __restrict__ Qg = g_Q + (bh * SQ + q0) * DH;
    const float* __restrict__ Kg = g_K + bh * SQ * DH;
    const float* __restrict__ Vg = g_V + bh * SQ * DH;

    // Load Q tile pre-scaled
    for (int idx = tid; idx < 64 * DH; idx += 256) {
        int r = idx / DH, d = idx % DH;
        Qs[r * QS_STRIDE + d] = Qg[idx] * scale;
    }

    float m_i[4], l_i[4], o[4][6];
    #pragma unroll
    for (int i = 0; i < 4; i++) {
        m_i[i] = -1e30f;
        l_i[i] = 0.0f;
        #pragma unroll
        for (int k = 0; k < 6; k++) o[i][k] = 0.0f;
    }

    for (int kt = 0; kt < SQ; kt += 64) {
        __syncthreads();   // protect Ks/Vs/Ps reuse from previous iteration
        for (int idx = tid; idx < 64 * DH; idx += 256) {
            int r = idx / DH, d = idx % DH;
            Ks[r * QS_STRIDE + d] = Kg[kt * DH + idx];
            Vs[r * QS_STRIDE + d] = Vg[kt * DH + idx];
        }
        __syncthreads();

        // Scores: 4x4 microtile, rows = ty*4.., cols = tx*4..
        float acc[4][4] = {};
        #pragma unroll 4
        for (int d = 0; d < DH; d++) {
            float a[4], b[4];
            #pragma unroll
            for (int i = 0; i < 4; i++) a[i] = Qs[(ty * 4 + i) * QS_STRIDE + d];
            #pragma unroll
            for (int j = 0; j < 4; j++) b[j] = Ks[(tx * 4 + j) * QS_STRIDE + d];
            #pragma unroll
            for (int i = 0; i < 4; i++)
                #pragma unroll
                for (int j = 0; j < 4; j++)
                    acc[i][j] += a[i] * b[j];
        }

        // Online softmax per row (each row owned by 16 lanes with same ty)
        #pragma unroll
        for (int i = 0; i < 4; i++) {
            float mx = acc[i][0];
            #pragma unroll
            for (int j = 1; j < 4; j++) mx = fmaxf(mx, acc[i][j]);
            #pragma unroll
            for (int off = 8; off >= 1; off >>= 1)
                mx = fmaxf(mx, __shfl_xor_sync(0xffffffffu, mx, off));

            float mnew = fmaxf(m_i[i], mx);
            float corr = __expf(m_i[i] - mnew);
            float rs = 0.0f;
            #pragma unroll
            for (int j = 0; j < 4; j++) {
                float p = __expf(acc[i][j] - mnew);
                acc[i][j] = p;
                rs += p;
            }
            #pragma unroll
            for (int off = 8; off >= 1; off >>= 1)
                rs += __shfl_xor_sync(0xffffffffu, rs, off);

            l_i[i] = l_i[i] * corr + rs;
            m_i[i] = mnew;
            #pragma unroll
            for (int k = 0; k < 6; k++) o[i][k] *= corr;

            #pragma unroll
            for (int j = 0; j < 4; j++)
                Ps[(ty * 4 + i) * PS_STRIDE + tx * 4 + j] = acc[i][j];
        }
        __syncthreads();

        // O += P @ V  (thread owns rows ty*4.., dims tx + 16*k for k<6)
        #pragma unroll 2
        for (int j = 0; j < 64; j++) {
            float p[4];
            #pragma unroll
            for (int i = 0; i < 4; i++) p[i] = Ps[(ty * 4 + i) * PS_STRIDE + j];
            #pragma unroll
            for (int k = 0; k < 6; k++) {
                float v = Vs[j * QS_STRIDE + (k * 16 + tx)];
                #pragma unroll
                for (int i = 0; i < 4; i++) o[i][k] += p[i] * v;
            }
        }
    }

    // Normalize + write
    float* __restrict__ Og = g_O + (bh * SQ + q0) * DH;
    #pragma unroll
    for (int i = 0; i < 4; i++) {
        float inv = 1.0f / l_i[i];
        int r = ty * 4 + i;
        #pragma unroll
        for (int k = 0; k < 6; k++)
            Og[r * DH + k * 16 + tx] = o[i][k] * inv;
    }
}

// ---------------------------------------------------------------------------
// Kernel 3: output projection.
// out[m][n] = sum_c cat[m][c] * Wo[c][n] + bo[n]
// cat[m][c] = g_O[((b*8 + c/96)*2048 + s)*96 + c%96], m = b*2048+s
// ---------------------------------------------------------------------------
__global__ __launch_bounds__(256) void oproj_kernel(
    const float* __restrict__ Wo, const float* __restrict__ bo,
    float* __restrict__ out)
{
    __shared__ float As[16][68];
    __shared__ float Bs[16][68];

    const int m0 = blockIdx.y * 64;
    const int n0 = blockIdx.x * 64;
    const int tid = threadIdx.x;
    const int tx = tid & 15;
    const int ty = tid >> 4;

    float acc[4][4] = {};

    for (int k0 = 0; k0 < DM; k0 += 16) {
        // A tile: cat[m][c], c = k0 + (idx&15). A 16-chunk never crosses a
        // head boundary (96 % 16 == 0), so the head is constant per chunk.
        #pragma unroll
        for (int i = 0; i < 4; i++) {
            int idx = tid + i * 256;
            int ml = idx >> 4, k = idx & 15;
            int m = m0 + ml;
            int c = k0 + k;
            int b = m >> 11, s = m & 2047;
            int h = c / DH, kk = c % DH;
            As[k][ml] = g_O[(((b * NH) + h) * SQ + s) * DH + kk];
        }
        #pragma unroll
        for (int i = 0; i < 4; i++) {
            int idx = tid + i * 256;
            int c = idx & 63, k = idx >> 6;
            Bs[k][c] = Wo[(k0 + k) * DM + n0 + c];
        }
        __syncthreads();

        #pragma unroll
        for (int k = 0; k < 16; k++) {
            float4 a = *(const float4*)&As[k][ty * 4];
            float4 b = *(const float4*)&Bs[k][tx * 4];
            float av[4] = {a.x, a.y, a.z, a.w};
            float bv4[4] = {b.x, b.y, b.z, b.w};
            #pragma unroll
            for (int i = 0; i < 4; i++)
                #pragma unroll
                for (int j = 0; j < 4; j++)
                    acc[i][j] += av[i] * bv4[j];
        }
        __syncthreads();
    }

    #pragma unroll
    for (int i = 0; i < 4; i++) {
        int m = m0 + ty * 4 + i;
        #pragma unroll
        for (int j = 0; j < 4; j++) {
            int n = n0 + tx * 4 + j;
            out[m * DM + n] = acc[i][j] + bo[n];
        }
    }
}

// ---------------------------------------------------------------------------
extern "C" void kernel_launch(void* const* d_in, const int* in_sizes, int n_in,
                              void* d_out, int out_size)
{
    const float* xq = (const float*)d_in[0];
    const float* xk = (const float*)d_in[1];
    const float* xv = (const float*)d_in[2];
    const float* Wq = (const float*)d_in[3];
    const float* bq = (const float*)d_in[4];
    const float* Wk = (const float*)d_in[5];
    const float* bk = (const float*)d_in[6];
    const float* Wv = (const float*)d_in[7];
    const float* bv = (const float*)d_in[8];
    const float* Wo = (const float*)d_in[9];
    const float* bo = (const float*)d_in[10];
    float* out = (float*)d_out;

    // QKV projections
    qkv_kernel<<<dim3(DM / 64, M_TOT / 64, 3), 256>>>(
        xq, xk, xv, Wq, Wk, Wv, bq, bk, bv);

    // Attention (needs >48KB dynamic smem; idempotent attribute set each call)
    cudaFuncSetAttribute(attn_kernel,
                         cudaFuncAttributeMaxDynamicSharedMemorySize, ATTN_SMEM);
    attn_kernel<<<dim3(SQ / 64, NB * NH), 256, ATTN_SMEM>>>();

    // Output projection
    oproj_kernel<<<dim3(DM / 64, M_TOT / 64), 256>>>(Wo, bo, out);
}

// round 3
// speedup vs baseline: 2.7736x; 2.7736x over previous
#include <cuda_runtime.h>
#include <math.h>
#include <stdint.h>

#define NB 4
#define NH 8
#define SQ 2048
#define DM 768
#define DH 96
#define M_TOT (NB*SQ)
#define QKV_ELEMS (NB*NH*SQ*DH)

__device__ float g_Q[QKV_ELEMS];
__device__ float g_K[QKV_ELEMS];
__device__ float g_V[QKV_ELEMS];
__device__ float g_O[QKV_ELEMS];

__device__ __forceinline__ uint32_t f2tf(float x){
    uint32_t r; asm("cvt.rna.tf32.f32 %0, %1;" : "=r"(r) : "f"(x)); return r;
}

__device__ __forceinline__ void mma8(float* c, const uint32_t* a, uint32_t b0, uint32_t b1){
    asm volatile("mma.sync.aligned.m16n8k8.row.col.f32.tf32.tf32.f32 "
        "{%0,%1,%2,%3}, {%4,%5,%6,%7}, {%8,%9}, {%0,%1,%2,%3};"
        : "+f"(c[0]),"+f"(c[1]),"+f"(c[2]),"+f"(c[3])
        : "r"(a[0]),"r"(a[1]),"r"(a[2]),"r"(a[3]),"r"(b0),"r"(b1));
}

// ---------------------------------------------------------------------------
// Projection GEMM tiles: 128x128, 256 threads (8 warps = 4M x 2N), warp 32x64.
// smem: A [128][20] tf32 (pad->conflict-free frag loads), B [16][136].
// ---------------------------------------------------------------------------
#define AS_STRIDE 20
#define BS_STRIDE 136
#define AS_BUF (128*AS_STRIDE)
#define BS_BUF (16*BS_STRIDE)

__global__ __launch_bounds__(256,2) void qkv_kernel(
    const float* __restrict__ Xq, const float* __restrict__ Xk, const float* __restrict__ Xv,
    const float* __restrict__ Wq, const float* __restrict__ Wk, const float* __restrict__ Wv,
    const float* __restrict__ bq, const float* __restrict__ bk, const float* __restrict__ bv)
{
    const int which = blockIdx.z;
    const float* __restrict__ X    = (which == 0) ? Xq : (which == 1) ? Xk : Xv;
    const float* __restrict__ W    = (which == 0) ? Wq : (which == 1) ? Wk : Wv;
    const float* __restrict__ bias = (which == 0) ? bq : (which == 1) ? bk : bv;
    float* __restrict__ out        = (which == 0) ? g_Q : (which == 1) ? g_K : g_V;

    __shared__ uint32_t As[2*AS_BUF];
    __shared__ uint32_t Bs[2*BS_BUF];

    const int tid = threadIdx.x;
    const int lane = tid & 31, wid = tid >> 5;
    const int grp = lane >> 2, tig = lane & 3;
    const int wm = wid & 3, wn = wid >> 2;
    const int m0 = blockIdx.y * 128, c0 = blockIdx.x * 128;

    // ldg assignments
    const int am = tid >> 1, ak = (tid & 1) * 8;
    const int bkr = tid >> 5, bn = (tid & 31) * 4;
    const float* Ab_g = X + (m0 + am) * DM;
    const int cW = c0 + bn;
    const float* Wb_g = W + (cW / DH) * (DM * DH) + (cW % DH);

    float4 ra0, ra1, rb0, rb1;
    float acc[2][8][4] = {};

    // prologue: chunk 0
    ra0 = *(const float4*)&Ab_g[ak];
    ra1 = *(const float4*)&Ab_g[ak + 4];
    rb0 = *(const float4*)&Wb_g[bkr * DH];
    rb1 = *(const float4*)&Wb_g[(bkr + 8) * DH];
    {
        uint4 u; uint32_t* Ap = As; uint32_t* Bp = Bs;
        u.x=f2tf(ra0.x); u.y=f2tf(ra0.y); u.z=f2tf(ra0.z); u.w=f2tf(ra0.w);
        *(uint4*)&Ap[am*AS_STRIDE + ak] = u;
        u.x=f2tf(ra1.x); u.y=f2tf(ra1.y); u.z=f2tf(ra1.z); u.w=f2tf(ra1.w);
        *(uint4*)&Ap[am*AS_STRIDE + ak + 4] = u;
        u.x=f2tf(rb0.x); u.y=f2tf(rb0.y); u.z=f2tf(rb0.z); u.w=f2tf(rb0.w);
        *(uint4*)&Bp[bkr*BS_STRIDE + bn] = u;
        u.x=f2tf(rb1.x); u.y=f2tf(rb1.y); u.z=f2tf(rb1.z); u.w=f2tf(rb1.w);
        *(uint4*)&Bp[(bkr+8)*BS_STRIDE + bn] = u;
    }
    __syncthreads();

    for (int ch = 0; ch < 48; ch++) {
        int k0n = (ch + 1) * 16;
        if (ch + 1 < 48) {
            ra0 = *(const float4*)&Ab_g[k0n + ak];
            ra1 = *(const float4*)&Ab_g[k0n + ak + 4];
            rb0 = *(const float4*)&Wb_g[(k0n + bkr) * DH];
            rb1 = *(const float4*)&Wb_g[(k0n + bkr + 8) * DH];
        }
        // compute current buffer
        {
            const uint32_t* Ap = As + (ch & 1) * AS_BUF;
            const uint32_t* Bp = Bs + (ch & 1) * BS_BUF;
            #pragma unroll
            for (int s8 = 0; s8 < 2; s8++) {
                int k8 = s8 * 8;
                uint32_t a[2][4];
                #pragma unroll
                for (int mt = 0; mt < 2; mt++) {
                    const uint32_t* ap = Ap + (wm*32 + mt*16 + grp)*AS_STRIDE + k8 + tig;
                    a[mt][0] = ap[0];
                    a[mt][2] = ap[4];
                    a[mt][1] = ap[8*AS_STRIDE];
                    a[mt][3] = ap[8*AS_STRIDE + 4];
                }
                #pragma unroll
                for (int nt = 0; nt < 8; nt++) {
                    int cb = wn*64 + nt*8 + grp;
                    uint32_t b0 = Bp[(k8 + tig)*BS_STRIDE + cb];
                    uint32_t b1 = Bp[(k8 + tig + 4)*BS_STRIDE + cb];
                    mma8(acc[0][nt], a[0], b0, b1);
                    mma8(acc[1][nt], a[1], b0, b1);
                }
            }
        }
        if (ch + 1 < 48) {
            uint32_t* Ap = As + ((ch+1) & 1) * AS_BUF;
            uint32_t* Bp = Bs + ((ch+1) & 1) * BS_BUF;
            uint4 u;
            u.x=f2tf(ra0.x); u.y=f2tf(ra0.y); u.z=f2tf(ra0.z); u.w=f2tf(ra0.w);
            *(uint4*)&Ap[am*AS_STRIDE + ak] = u;
            u.x=f2tf(ra1.x); u.y=f2tf(ra1.y); u.z=f2tf(ra1.z); u.w=f2tf(ra1.w);
            *(uint4*)&Ap[am*AS_STRIDE + ak + 4] = u;
            u.x=f2tf(rb0.x); u.y=f2tf(rb0.y); u.z=f2tf(rb0.z); u.w=f2tf(rb0.w);
            *(uint4*)&Bp[bkr*BS_STRIDE + bn] = u;
            u.x=f2tf(rb1.x); u.y=f2tf(rb1.y); u.z=f2tf(rb1.z); u.w=f2tf(rb1.w);
            *(uint4*)&Bp[(bkr+8)*BS_STRIDE + bn] = u;
            __syncthreads();
        }
    }

    // epilogue: scatter to [B,H,S,DH] with bias
    #pragma unroll
    for (int nt = 0; nt < 8; nt++) {
        int col = c0 + wn*64 + nt*8 + 2*tig;
        int h = col / DH, kk = col - h*DH;
        float b0v = bias[col], b1v = bias[col + 1];
        #pragma unroll
        for (int mt = 0; mt < 2; mt++) {
            int r = m0 + wm*32 + mt*16 + grp;
            int b = r >> 11, s = r & 2047;
            float* o0 = &out[(((b*NH) + h)*SQ + s)*DH + kk];
            *(float2*)o0 = make_float2(acc[mt][nt][0] + b0v, acc[mt][nt][1] + b1v);
            float* o1 = &out[(((b*NH) + h)*SQ + (s + 8 < SQ ? s : s))*DH + kk]; (void)o1;
            int r2 = r + 8;
            int b2 = r2 >> 11, s2 = r2 & 2047;
            float* o2 = &out[(((b2*NH) + h)*SQ + s2)*DH + kk];
            *(float2*)o2 = make_float2(acc[mt][nt][2] + b0v, acc[mt][nt][3] + b1v);
        }
    }
}

__global__ __launch_bounds__(256,2) void oproj_kernel(
    const float* __restrict__ Wo, const float* __restrict__ bo,
    float* __restrict__ out)
{
    __shared__ uint32_t As[2*AS_BUF];
    __shared__ uint32_t Bs[2*BS_BUF];

    const int tid = threadIdx.x;
    const int lane = tid & 31, wid = tid >> 5;
    const int grp = lane >> 2, tig = lane & 3;
    const int wm = wid & 3, wn = wid >> 2;
    const int m0 = blockIdx.y * 128, n0 = blockIdx.x * 128;

    const int am = tid >> 1, ak = (tid & 1) * 8;
    const int bkr = tid >> 5, bn = (tid & 31) * 4;
    const int mg = m0 + am;
    const int bb = mg >> 11, ss = mg & 2047;

    float4 ra0, ra1, rb0, rb1;
    float acc[2][8][4] = {};

    // A gather base recomputed per chunk (head changes with k)
    #define LDG_OP(k0) { \
        int c = (k0) + ak; int h = c / DH; int kk = c - h*DH; \
        const float* ap = &g_O[(((bb*NH) + h)*SQ + ss)*DH + kk]; \
        ra0 = *(const float4*)ap; ra1 = *(const float4*)(ap + 4); \
        rb0 = *(const float4*)&Wo[((k0) + bkr)*DM + n0 + bn]; \
        rb1 = *(const float4*)&Wo[((k0) + bkr + 8)*DM + n0 + bn]; }
    #define STS_OP(buf) { \
        uint32_t* Ap = As + (buf)*AS_BUF; uint32_t* Bp = Bs + (buf)*BS_BUF; uint4 u; \
        u.x=f2tf(ra0.x); u.y=f2tf(ra0.y); u.z=f2tf(ra0.z); u.w=f2tf(ra0.w); \
        *(uint4*)&Ap[am*AS_STRIDE + ak] = u; \
        u.x=f2tf(ra1.x); u.y=f2tf(ra1.y); u.z=f2tf(ra1.z); u.w=f2tf(ra1.w); \
        *(uint4*)&Ap[am*AS_STRIDE + ak + 4] = u; \
        u.x=f2tf(rb0.x); u.y=f2tf(rb0.y); u.z=f2tf(rb0.z); u.w=f2tf(rb0.w); \
        *(uint4*)&Bp[bkr*BS_STRIDE + bn] = u; \
        u.x=f2tf(rb1.x); u.y=f2tf(rb1.y); u.z=f2tf(rb1.z); u.w=f2tf(rb1.w); \
        *(uint4*)&Bp[(bkr+8)*BS_STRIDE + bn] = u; }

    LDG_OP(0); STS_OP(0);
    __syncthreads();

    for (int ch = 0; ch < 48; ch++) {
        int k0n = (ch + 1) * 16;
        if (ch + 1 < 48) LDG_OP(k0n);
        {
            const uint32_t* Ap = As + (ch & 1) * AS_BUF;
            const uint32_t* Bp = Bs + (ch & 1) * BS_BUF;
            #pragma unroll
            for (int s8 = 0; s8 < 2; s8++) {
                int k8 = s8 * 8;
                uint32_t a[2][4];
                #pragma unroll
                for (int mt = 0; mt < 2; mt++) {
                    const uint32_t* ap = Ap + (wm*32 + mt*16 + grp)*AS_STRIDE + k8 + tig;
                    a[mt][0] = ap[0];
                    a[mt][2] = ap[4];
                    a[mt][1] = ap[8*AS_STRIDE];
                    a[mt][3] = ap[8*AS_STRIDE + 4];
                }
                #pragma unroll
                for (int nt = 0; nt < 8; nt++) {
                    int cb = wn*64 + nt*8 + grp;
                    uint32_t b0 = Bp[(k8 + tig)*BS_STRIDE + cb];
                    uint32_t b1 = Bp[(k8 + tig + 4)*BS_STRIDE + cb];
                    mma8(acc[0][nt], a[0], b0, b1);
                    mma8(acc[1][nt], a[1], b0, b1);
                }
            }
        }
        if (ch + 1 < 48) { STS_OP((ch + 1) & 1); __syncthreads(); }
    }
    #undef LDG_OP
    #undef STS_OP

    #pragma unroll
    for (int nt = 0; nt < 8; nt++) {
        int col = n0 + wn*64 + nt*8 + 2*tig;
        float b0v = bo[col], b1v = bo[col + 1];
        #pragma unroll
        for (int mt = 0; mt < 2; mt++) {
            int r = m0 + wm*32 + mt*16 + grp;
            *(float2*)&out[r*DM + col] = make_float2(acc[mt][nt][0] + b0v, acc[mt][nt][1] + b1v);
            *(float2*)&out[(r+8)*DM + col] = make_float2(acc[mt][nt][2] + b0v, acc[mt][nt][3] + b1v);
        }
    }
}

// ---------------------------------------------------------------------------
// Flash attention, tf32 mma. Br=128, Bc=64, 8 warps (16 rows each).
// Q fragments live in registers. K/V/P stored in pair-interleaved float2
// layouts so every fragment load is a single conflict-free LDS.64.
// ---------------------------------------------------------------------------
#define KS2_FLOATS (48*136)   // 12 ksteps x 4 tig rows, stride 68 float2
#define VS2_FLOATS (32*200)   //  8 ksteps x 4,          stride 100 float2
#define PS2_FLOATS (128*72)   // 128 rows,               stride 36 float2
#define ATTN_SMEM ((KS2_FLOATS + VS2_FLOATS + PS2_FLOATS) * 4)

__global__ __launch_bounds__(256) void attn_kernel()
{
    extern __shared__ uint32_t sm[];
    uint32_t* Ks2 = sm;
    uint32_t* Vs2 = sm + KS2_FLOATS;
    uint32_t* Ps2 = Vs2 + VS2_FLOATS;

    const int bh = blockIdx.y;
    const int q0 = blockIdx.x * 128;
    const int tid = threadIdx.x, lane = tid & 31, w = tid >> 5;
    const int grp = lane >> 2, tig = lane & 3;
    const float scale = 0.1020620726f;   // 1/sqrt(96)

    const float* __restrict__ Qg = g_Q + (bh * SQ + q0) * DH;
    const float* __restrict__ Kg = g_K + bh * SQ * DH;
    const float* __restrict__ Vg = g_V + bh * SQ * DH;

    const int r0l = w * 16 + grp;     // local row (a0/a2)
    const int r1l = r0l + 8;          // a1/a3

    // Q fragments (pre-scaled, tf32) resident in registers
    uint32_t qf[12][4];
    #pragma unroll
    for (int ks = 0; ks < 12; ks++) {
        int cA = ks * 8 + tig;
        qf[ks][0] = f2tf(Qg[r0l*DH + cA] * scale);
        qf[ks][1] = f2tf(Qg[r1l*DH + cA] * scale);
        qf[ks][2] = f2tf(Qg[r0l*DH + cA + 4] * scale);
        qf[ks][3] = f2tf(Qg[r1l*DH + cA + 4] * scale);
    }

    float o[12][4];
    #pragma unroll
    for (int nt = 0; nt < 12; nt++) { o[nt][0]=o[nt][1]=o[nt][2]=o[nt][3]=0.f; }
    float m0r = -1e30f, m1r = -1e30f, l0 = 0.f, l1 = 0.f;

    for (int kt = 0; kt < SQ; kt += 64) {
        __syncthreads();
        // Load K,V tile (64x96) into pair-interleaved smem
        #pragma unroll
        for (int p = 0; p < 6; p++) {
            int i = tid + p * 256;          // 0..1535 (float4 index)
            int j = i / 24, d4 = (i - j*24) * 4;
            float4 kv = *(const float4*)&Kg[(kt + j)*DH + d4];
            float4 vv = *(const float4*)&Vg[(kt + j)*DH + d4];
            int vrow = (j >> 3)*4 + (j & 3), vhalf = (j >> 2) & 1;
            float kvv[4] = {kv.x, kv.y, kv.z, kv.w};
            float vvv[4] = {vv.x, vv.y, vv.z, vv.w};
            #pragma unroll
            for (int e = 0; e < 4; e++) {
                int d = d4 + e;
                Ks2[((d >> 3)*4 + (d & 3))*136 + j*2 + ((d >> 2) & 1)] = f2tf(kvv[e]);
                Vs2[vrow*200 + d*2 + vhalf] = f2tf(vvv[e]);
            }
        }
        __syncthreads();

        // S = Q K^T
        float s[8][4];
        #pragma unroll
        for (int nt = 0; nt < 8; nt++) { s[nt][0]=s[nt][1]=s[nt][2]=s[nt][3]=0.f; }
        #pragma unroll
        for (int ks = 0; ks < 12; ks++) {
            #pragma unroll
            for (int nt = 0; nt < 8; nt++) {
                uint2 b = *(const uint2*)&Ks2[((ks*4 + tig)*68 + nt*8 + grp)*2];
                mma8(s[nt], qf[ks], b.x, b.y);
            }
        }

        // online softmax (rows r0l, r1l; 4 lanes per row share via shfl over tig)
        float mx0 = -1e30f, mx1 = -1e30f;
        #pragma unroll
        for (int nt = 0; nt < 8; nt++) {
            mx0 = fmaxf(mx0, fmaxf(s[nt][0], s[nt][1]));
            mx1 = fmaxf(mx1, fmaxf(s[nt][2], s[nt][3]));
        }
        mx0 = fmaxf(mx0, __shfl_xor_sync(0xffffffffu, mx0, 1));
        mx0 = fmaxf(mx0, __shfl_xor_sync(0xffffffffu, mx0, 2));
        mx1 = fmaxf(mx1, __shfl_xor_sync(0xffffffffu, mx1, 1));
        mx1 = fmaxf(mx1, __shfl_xor_sync(0xffffffffu, mx1, 2));
        float mn0 = fmaxf(m0r, mx0), mn1 = fmaxf(m1r, mx1);
        float c0f = __expf(m0r - mn0), c1f = __expf(m1r - mn1);
        m0r = mn0; m1r = mn1;

        float rs0 = 0.f, rs1 = 0.f;
        const int cc0 = 2*tig, cc1 = 2*tig + 1;
        const int sl0 = (cc0 & 3)*2 + (cc0 >> 2);
        const int sl1 = (cc1 & 3)*2 + (cc1 >> 2);
        #pragma unroll
        for (int nt = 0; nt < 8; nt++) {
            float p00 = __expf(s[nt][0] - mn0);
            float p01 = __expf(s[nt][1] - mn0);
            float p10 = __expf(s[nt][2] - mn1);
            float p11 = __expf(s[nt][3] - mn1);
            rs0 += p00 + p01; rs1 += p10 + p11;
            Ps2[r0l*72 + nt*8 + sl0] = f2tf(p00);
            Ps2[r0l*72 + nt*8 + sl1] = f2tf(p01);
            Ps2[r1l*72 + nt*8 + sl0] = f2tf(p10);
            Ps2[r1l*72 + nt*8 + sl1] = f2tf(p11);
        }
        rs0 += __shfl_xor_sync(0xffffffffu, rs0, 1);
        rs0 += __shfl_xor_sync(0xffffffffu, rs0, 2);
        rs1 += __shfl_xor_sync(0xffffffffu, rs1, 1);
        rs1 += __shfl_xor_sync(0xffffffffu, rs1, 2);
        l0 = l0 * c0f + rs0;
        l1 = l1 * c1f + rs1;
        #pragma unroll
        for (int nt = 0; nt < 12; nt++) {
            o[nt][0] *= c0f; o[nt][1] *= c0f;
            o[nt][2] *= c1f; o[nt][3] *= c1f;
        }
        __syncwarp();   // Ps rows are warp-local: warp-level ordering suffices

        // O += P V
        #pragma unroll
        for (int ks2 = 0; ks2 < 8; ks2++) {
            uint32_t a[4];
            uint2 a02 = *(const uint2*)&Ps2[(r0l*36 + ks2*4 + tig)*2];
            uint2 a13 = *(const uint2*)&Ps2[(r1l*36 + ks2*4 + tig)*2];
            a[0] = a02.x; a[2] = a02.y; a[1] = a13.x; a[3] = a13.y;
            #pragma unroll
            for (int nt = 0; nt < 12; nt++) {
                uint2 b = *(const uint2*)&Vs2[((ks2*4 + tig)*100 + nt*8 + grp)*2];
                mma8(o[nt], a, b.x, b.y);
            }
        }
    }

    // epilogue
    float inv0 = 1.f / l0, inv1 = 1.f / l1;
    float* __restrict__ Og = g_O + (bh * SQ + q0) * DH;
    #pragma unroll
    for (int nt = 0; nt < 12; nt++) {
        int d0 = nt*8 + 2*tig;
        *(float2*)&Og[r0l*DH + d0] = make_float2(o[nt][0]*inv0, o[nt][1]*inv0);
        *(float2*)&Og[r1l*DH + d0] = make_float2(o[nt][2]*inv1, o[nt][3]*inv1);
    }
}

// ---------------------------------------------------------------------------
extern "C" void kernel_launch(void* const* d_in, const int* in_sizes, int n_in,
                              void* d_out, int out_size)
{
    const float* xq = (const float*)d_in[0];
    const float* xk = (const float*)d_in[1];
    const float* xv = (const float*)d_in[2];
    const float* Wq = (const float*)d_in[3];
    const float* bq = (const float*)d_in[4];
    const float* Wk = (const float*)d_in[5];
    const float* bk = (const float*)d_in[6];
    const float* Wv = (const float*)d_in[7];
    const float* bv = (const float*)d_in[8];
    const float* Wo = (const float*)d_in[9];
    const float* bo = (const float*)d_in[10];
    float* out = (float*)d_out;

    qkv_kernel<<<dim3(DM/128, M_TOT/128, 3), 256>>>(
        xq, xk, xv, Wq, Wk, Wv, bq, bk, bv);

    cudaFuncSetAttribute(attn_kernel,
                         cudaFuncAttributeMaxDynamicSharedMemorySize, ATTN_SMEM);
    attn_kernel<<<dim3(SQ/128, NB*NH), 256, ATTN_SMEM>>>();

    oproj_kernel<<<dim3(DM/128, M_TOT/128), 256>>>(Wo, bo, out);
}

// round 5
// speedup vs baseline: 4.3811x; 1.5796x over previous
#include <cuda_runtime.h>
#include <math.h>
#include <stdint.h>

#define NB 4
#define NH 8
#define SQ 2048
#define DM 768
#define DH 96
#define M_TOT (NB*SQ)
#define QKV_ELEMS (NB*NH*SQ*DH)
#define SCALE 0.1020620726f   // 1/sqrt(96)

// Scratch. g_Q: [bh][s][dperm]  (d permuted within 8-blocks, pre-scaled, tf32-rounded)
//          g_K: [bh][r(48)][j*2+h]  transposed pair-interleaved, tf32-rounded
//          g_V: [bh][jb(256)][d(96)][jperm(8)], tf32-rounded
//          g_O: [bh][s][d] plain fp32
__device__ float g_Q[QKV_ELEMS];
__device__ float g_K[QKV_ELEMS];
__device__ float g_V[QKV_ELEMS];
__device__ float g_O[QKV_ELEMS];

__device__ __forceinline__ uint32_t f2tf(float x){
    uint32_t r; asm("cvt.rna.tf32.f32 %0, %1;" : "=r"(r) : "f"(x)); return r;
}
__device__ __forceinline__ float f2tff(float x){
    return __uint_as_float(f2tf(x));
}
__device__ __forceinline__ uint4 cvt4(float4 v){
    uint4 u; u.x=f2tf(v.x); u.y=f2tf(v.y); u.z=f2tf(v.z); u.w=f2tf(v.w); return u;
}
__device__ __forceinline__ void mma8(float* c, const uint32_t* a, uint32_t b0, uint32_t b1){
    asm volatile("mma.sync.aligned.m16n8k8.row.col.f32.tf32.tf32.f32 "
        "{%0,%1,%2,%3}, {%4,%5,%6,%7}, {%8,%9}, {%0,%1,%2,%3};"
        : "+f"(c[0]),"+f"(c[1]),"+f"(c[2]),"+f"(c[3])
        : "r"(a[0]),"r"(a[1]),"r"(a[2]),"r"(a[3]),"r"(b0),"r"(b1));
}

// ---------------------------------------------------------------------------
// Projection GEMMs: CTA 128x128, 128 threads (4 warps, 2x2), warp tile 64x64.
// K-chunk 16, double buffered via register staging (fp32 -> rna tf32 -> smem).
// ---------------------------------------------------------------------------
#define AS_STRIDE 20
#define BS_STRIDE 136
#define AS_BUF (128*AS_STRIDE)
#define BS_BUF (16*BS_STRIDE)

__global__ __launch_bounds__(128,2) void qkv_kernel(
    const float* __restrict__ Xq, const float* __restrict__ Xk, const float* __restrict__ Xv,
    const float* __restrict__ Wq, const float* __restrict__ Wk, const float* __restrict__ Wv,
    const float* __restrict__ bq, const float* __restrict__ bk, const float* __restrict__ bv)
{
    const int which = blockIdx.z;
    const float* __restrict__ X    = (which == 0) ? Xq : (which == 1) ? Xk : Xv;
    const float* __restrict__ W    = (which == 0) ? Wq : (which == 1) ? Wk : Wv;
    const float* __restrict__ bias = (which == 0) ? bq : (which == 1) ? bk : bv;
    float* __restrict__ out        = (which == 0) ? g_Q : (which == 1) ? g_K : g_V;

    __shared__ uint32_t As[2*AS_BUF];
    __shared__ uint32_t Bs[2*BS_BUF];

    const int tid = threadIdx.x;
    const int lane = tid & 31, wid = tid >> 5;
    const int grp = lane >> 2, tig = lane & 3;
    const int wm = wid & 1, wn = wid >> 1;
    const int m0 = blockIdx.y * 128, c0 = blockIdx.x * 128;

    // LDG assignments
    const int arow = tid >> 2, akq = (tid & 3) * 4;   // + 32*i rows
    const int bkr = tid >> 5, bcol4 = (tid & 31) * 4; // + 4*i k-rows
    const int cW = c0 + bcol4;
    const int hW = cW / DH, ddW = cW - hW * DH;
    const float* Wb = W + hW * (DM * DH) + ddW;

    float4 ra[4], rb[4];
    float acc[4][8][4] = {};

    #define LDG_OP(k0) { \
        _Pragma("unroll") for (int i = 0; i < 4; i++) { \
            ra[i] = *(const float4*)&X[(m0 + arow + 32*i)*DM + (k0) + akq]; \
            rb[i] = *(const float4*)&Wb[((k0) + bkr + 4*i)*DH]; } }
    #define STS_OP(buf) { \
        uint32_t* Ap = As + (buf)*AS_BUF; uint32_t* Bp = Bs + (buf)*BS_BUF; \
        _Pragma("unroll") for (int i = 0; i < 4; i++) { \
            *(uint4*)&Ap[(arow + 32*i)*AS_STRIDE + akq] = cvt4(ra[i]); \
            *(uint4*)&Bp[(bkr + 4*i)*BS_STRIDE + bcol4] = cvt4(rb[i]); } }

    LDG_OP(0); STS_OP(0);
    __syncthreads();

    for (int ch = 0; ch < 48; ch++) {
        if (ch + 1 < 48) LDG_OP((ch + 1) * 16);
        {
            const uint32_t* Ap = As + (ch & 1) * AS_BUF;
            const uint32_t* Bp = Bs + (ch & 1) * BS_BUF;
            #pragma unroll
            for (int s8 = 0; s8 < 2; s8++) {
                int k8 = s8 * 8;
                uint32_t a[4][4];
                #pragma unroll
                for (int mt = 0; mt < 4; mt++) {
                    const uint32_t* ap = Ap + (wm*64 + mt*16 + grp)*AS_STRIDE + k8 + tig;
                    a[mt][0] = ap[0];
                    a[mt][2] = ap[4];
                    a[mt][1] = ap[8*AS_STRIDE];
                    a[mt][3] = ap[8*AS_STRIDE + 4];
                }
                #pragma unroll
                for (int nt = 0; nt < 8; nt++) {
                    int cb = wn*64 + nt*8 + grp;
                    uint32_t b0 = Bp[(k8 + tig)*BS_STRIDE + cb];
                    uint32_t b1 = Bp[(k8 + tig + 4)*BS_STRIDE + cb];
                    #pragma unroll
                    for (int mt = 0; mt < 4; mt++)
                        mma8(acc[mt][nt], a[mt], b0, b1);
                }
            }
        }
        if (ch + 1 < 48) { STS_OP((ch + 1) & 1); __syncthreads(); }
    }
    #undef LDG_OP
    #undef STS_OP

    // Epilogue: per-value scatter into the attention-friendly layouts.
    #pragma unroll
    for (int nt = 0; nt < 8; nt++) {
        int col = c0 + wn*64 + nt*8 + 2*tig;
        int h = col / DH, dd = col - h*DH;
        float bv0 = bias[col], bv1 = bias[col + 1];
        #pragma unroll
        for (int mt = 0; mt < 4; mt++) {
            int r = m0 + wm*64 + mt*16 + grp;
            #pragma unroll
            for (int rr = 0; rr < 2; rr++) {
                int rg = r + rr*8;
                int b = rg >> 11, s = rg & 2047;
                int bh = b*NH + h;
                float v0 = acc[mt][nt][rr*2 + 0] + bv0;
                float v1 = acc[mt][nt][rr*2 + 1] + bv1;
                if (which == 0) {
                    int base = (bh*SQ + s)*DH;
                    out[base + (dd>>3)*8 + ((dd&3)<<1) + ((dd>>2)&1)] = f2tff(v0*SCALE);
                    int d1 = dd + 1;
                    out[base + (d1>>3)*8 + ((d1&3)<<1) + ((d1>>2)&1)] = f2tff(v1*SCALE);
                } else if (which == 1) {
                    int base = bh*196608 + (s<<1);
                    out[base + (((dd>>3)<<2) + (dd&3))*4096 + ((dd>>2)&1)] = f2tff(v0);
                    int d1 = dd + 1;
                    out[base + (((d1>>3)<<2) + (d1&3))*4096 + ((d1>>2)&1)] = f2tff(v1);
                } else {
                    int base = bh*196608 + (s>>3)*768 + ((s&3)<<1) + ((s>>2)&1);
                    out[base + (dd<<3)] = f2tff(v0);
                    out[base + ((dd+1)<<3)] = f2tff(v1);
                }
            }
        }
    }
}

__global__ __launch_bounds__(128,2) void oproj_kernel(
    const float* __restrict__ Wo, const float* __restrict__ bo,
    float* __restrict__ out)
{
    __shared__ uint32_t As[2*AS_BUF];
    __shared__ uint32_t Bs[2*BS_BUF];

    const int tid = threadIdx.x;
    const int lane = tid & 31, wid = tid >> 5;
    const int grp = lane >> 2, tig = lane & 3;
    const int wm = wid & 1, wn = wid >> 1;
    const int m0 = blockIdx.y * 128, n0 = blockIdx.x * 128;

    const int arow = tid >> 2, akq = (tid & 3) * 4;
    const int bkr = tid >> 5, bcol4 = (tid & 31) * 4;

    float4 ra[4], rb[4];
    float acc[4][8][4] = {};

    #define LDG_OP(k0) { \
        int c = (k0) + akq; int h = c / DH; int dd = c - h*DH; \
        _Pragma("unroll") for (int i = 0; i < 4; i++) { \
            int m = m0 + arow + 32*i; int b = m >> 11; int s = m & 2047; \
            ra[i] = *(const float4*)&g_O[((b*NH + h)*SQ + s)*DH + dd]; \
            rb[i] = *(const float4*)&Wo[((k0) + bkr + 4*i)*DM + n0 + bcol4]; } }
    #define STS_OP(buf) { \
        uint32_t* Ap = As + (buf)*AS_BUF; uint32_t* Bp = Bs + (buf)*BS_BUF; \
        _Pragma("unroll") for (int i = 0; i < 4; i++) { \
            *(uint4*)&Ap[(arow + 32*i)*AS_STRIDE + akq] = cvt4(ra[i]); \
            *(uint4*)&Bp[(bkr + 4*i)*BS_STRIDE + bcol4] = cvt4(rb[i]); } }

    LDG_OP(0); STS_OP(0);
    __syncthreads();

    for (int ch = 0; ch < 48; ch++) {
        if (ch + 1 < 48) LDG_OP((ch + 1) * 16);
        {
            const uint32_t* Ap = As + (ch & 1) * AS_BUF;
            const uint32_t* Bp = Bs + (ch & 1) * BS_BUF;
            #pragma unroll
            for (int s8 = 0; s8 < 2; s8++) {
                int k8 = s8 * 8;
                uint32_t a[4][4];
                #pragma unroll
                for (int mt = 0; mt < 4; mt++) {
                    const uint32_t* ap = Ap + (wm*64 + mt*16 + grp)*AS_STRIDE + k8 + tig;
                    a[mt][0] = ap[0];
                    a[mt][2] = ap[4];
                    a[mt][1] = ap[8*AS_STRIDE];
                    a[mt][3] = ap[8*AS_STRIDE + 4];
                }
                #pragma unroll
                for (int nt = 0; nt < 8; nt++) {
                    int cb = wn*64 + nt*8 + grp;
                    uint32_t b0 = Bp[(k8 + tig)*BS_STRIDE + cb];
                    uint32_t b1 = Bp[(k8 + tig + 4)*BS_STRIDE + cb];
                    #pragma unroll
                    for (int mt = 0; mt < 4; mt++)
                        mma8(acc[mt][nt], a[mt], b0, b1);
                }
            }
        }
        if (ch + 1 < 48) { STS_OP((ch + 1) & 1); __syncthreads(); }
    }
    #undef LDG_OP
    #undef STS_OP

    #pragma unroll
    for (int nt = 0; nt < 8; nt++) {
        int col = n0 + wn*64 + nt*8 + 2*tig;
        float bv0 = bo[col], bv1 = bo[col + 1];
        #pragma unroll
        for (int mt = 0; mt < 4; mt++) {
            int r = m0 + wm*64 + mt*16 + grp;
            *(float2*)&out[r*DM + col] =
                make_float2(acc[mt][nt][0] + bv0, acc[mt][nt][1] + bv1);
            *(float2*)&out[(r+8)*DM + col] =
                make_float2(acc[mt][nt][2] + bv0, acc[mt][nt][3] + bv1);
        }
    }
}

// ---------------------------------------------------------------------------
// Flash attention: Br=128, Bc=64, 256 threads (8 warps x 16 rows).
// K/V streamed via cp.async into double-buffered smem (data pre-rounded by
// producer, so no cvt needed). Q fragments in registers. P kept in registers
// (C-frag -> A-frag conversion via shuffles). All frag loads are LDS.64,
// conflict-free.
// ---------------------------------------------------------------------------
#define KSM_F 6528   // 48 * 136 floats per buffer
#define VSM_F 6144   // 8 * 768 floats per buffer
#define ATTN_SMEM ((2*KSM_F + 2*VSM_F) * 4)   // 101376 B

__device__ __forceinline__ void cpa16(uint32_t dst, const float* src){
    asm volatile("cp.async.cg.shared.global [%0], [%1], 16;" :: "r"(dst), "l"(src));
}

__global__ __launch_bounds__(256) void attn_kernel()
{
    extern __shared__ float sm[];
    const int bh = blockIdx.y;
    const int q0 = blockIdx.x * 128;
    const int tid = threadIdx.x, lane = tid & 31, w = tid >> 5;
    const int grp = lane >> 2, tig = lane & 3;

    const float* __restrict__ Qg = g_Q + (bh * SQ + q0) * DH;
    const float* __restrict__ Kg = g_K + bh * 196608;
    const float* __restrict__ Vg = g_V + bh * 196608;

    const int r0l = w * 16 + grp, r1l = r0l + 8;
    const uint32_t smb = (uint32_t)__cvta_generic_to_shared(sm);

    // Q fragments (already scaled + tf32-rounded by producer)
    uint32_t qf[12][4];
    #pragma unroll
    for (int ks = 0; ks < 12; ks++) {
        uint2 u0 = *(const uint2*)&Qg[r0l*DH + ks*8 + tig*2];
        uint2 u1 = *(const uint2*)&Qg[r1l*DH + ks*8 + tig*2];
        qf[ks][0] = u0.x; qf[ks][2] = u0.y;
        qf[ks][1] = u1.x; qf[ks][3] = u1.y;
    }

    float o[12][4];
    #pragma unroll
    for (int nt = 0; nt < 12; nt++) { o[nt][0]=o[nt][1]=o[nt][2]=o[nt][3]=0.f; }
    float m0r = -1e30f, m1r = -1e30f, l0 = 0.f, l1 = 0.f;

    auto issue = [&](int t, int buf){
        #pragma unroll
        for (int i = 0; i < 6; i++) {
            int idx = tid + i*256;
            int r = idx >> 5, c4 = (idx & 31) << 2;
            cpa16(smb + (buf*KSM_F + r*136 + c4)*4, Kg + r*4096 + t*128 + c4);
        }
        #pragma unroll
        for (int i = 0; i < 6; i++) {
            int idx = tid + i*256;
            cpa16(smb + (2*KSM_F + buf*VSM_F + idx*4)*4, Vg + t*VSM_F + idx*4);
        }
        asm volatile("cp.async.commit_group;");
    };

    issue(0, 0);

    for (int t = 0; t < 32; t++) {
        __syncthreads();                 // all warps done with buf (t+1)&1
        if (t + 1 < 32) {
            issue(t + 1, (t + 1) & 1);
            asm volatile("cp.async.wait_group 1;");
        } else {
            asm volatile("cp.async.wait_group 0;");
        }
        __syncthreads();                 // tile t data visible to all

        const uint2* Kf = (const uint2*)(sm + (t & 1)*KSM_F);
        const uint2* Vf = (const uint2*)(sm + 2*KSM_F + (t & 1)*VSM_F);

        // S = Q K^T
        float s[8][4];
        #pragma unroll
        for (int nt = 0; nt < 8; nt++) { s[nt][0]=s[nt][1]=s[nt][2]=s[nt][3]=0.f; }
        #pragma unroll
        for (int ks = 0; ks < 12; ks++) {
            #pragma unroll
            for (int nt = 0; nt < 8; nt++) {
                uint2 b = Kf[(ks*4 + tig)*68 + nt*8 + grp];
                mma8(s[nt], qf[ks], b.x, b.y);
            }
        }

        // online softmax
        float mx0 = -1e30f, mx1 = -1e30f;
        #pragma unroll
        for (int nt = 0; nt < 8; nt++) {
            mx0 = fmaxf(mx0, fmaxf(s[nt][0], s[nt][1]));
            mx1 = fmaxf(mx1, fmaxf(s[nt][2], s[nt][3]));
        }
        mx0 = fmaxf(mx0, __shfl_xor_sync(0xffffffffu, mx0, 1));
        mx0 = fmaxf(mx0, __shfl_xor_sync(0xffffffffu, mx0, 2));
        mx1 = fmaxf(mx1, __shfl_xor_sync(0xffffffffu, mx1, 1));
        mx1 = fmaxf(mx1, __shfl_xor_sync(0xffffffffu, mx1, 2));
        float mn0 = fmaxf(m0r, mx0), mn1 = fmaxf(m1r, mx1);
        float c0f = __expf(m0r - mn0), c1f = __expf(m1r - mn1);
        m0r = mn0; m1r = mn1;

        // exp + C-frag -> A-frag via shuffles (P stays in registers)
        const int sl  = (grp << 2) + (tig >> 1);
        const int sl2 = sl + 2;
        const bool odd = (tig & 1);
        uint32_t pa[8][4];
        float rs0 = 0.f, rs1 = 0.f;
        #pragma unroll
        for (int nt = 0; nt < 8; nt++) {
            float p00 = __expf(s[nt][0] - mn0);
            float p01 = __expf(s[nt][1] - mn0);
            float p10 = __expf(s[nt][2] - mn1);
            float p11 = __expf(s[nt][3] - mn1);
            rs0 += p00 + p01; rs1 += p10 + p11;
            uint32_t u0 = f2tf(p00), u1 = f2tf(p01);
            uint32_t u2 = f2tf(p10), u3 = f2tf(p11);
            uint32_t t0 = __shfl_sync(0xffffffffu, u0, sl);
            uint32_t t1 = __shfl_sync(0xffffffffu, u1, sl);
            uint32_t t2 = __shfl_sync(0xffffffffu, u2, sl);
            uint32_t t3 = __shfl_sync(0xffffffffu, u3, sl);
            uint32_t t4 = __shfl_sync(0xffffffffu, u0, sl2);
            uint32_t t5 = __shfl_sync(0xffffffffu, u1, sl2);
            uint32_t t6 = __shfl_sync(0xffffffffu, u2, sl2);
            uint32_t t7 = __shfl_sync(0xffffffffu, u3, sl2);
            pa[nt][0] = odd ? t1 : t0;
            pa[nt][1] = odd ? t3 : t2;
            pa[nt][2] = odd ? t5 : t4;
            pa[nt][3] = odd ? t7 : t6;
        }
        rs0 += __shfl_xor_sync(0xffffffffu, rs0, 1);
        rs0 += __shfl_xor_sync(0xffffffffu, rs0, 2);
        rs1 += __shfl_xor_sync(0xffffffffu, rs1, 1);
        rs1 += __shfl_xor_sync(0xffffffffu, rs1, 2);
        l0 = l0 * c0f + rs0;
        l1 = l1 * c1f + rs1;
        #pragma unroll
        for (int nt = 0; nt < 12; nt++) {
            o[nt][0] *= c0f; o[nt][1] *= c0f;
            o[nt][2] *= c1f; o[nt][3] *= c1f;
        }

        // O += P V
        #pragma unroll
        for (int ks2 = 0; ks2 < 8; ks2++) {
            #pragma unroll
            for (int nt = 0; nt < 12; nt++) {
                uint2 b = Vf[ks2*384 + (nt*8 + grp)*4 + tig];
                mma8(o[nt], pa[ks2], b.x, b.y);
            }
        }
    }

    // epilogue -> g_O plain [bh][s][d] fp32
    float inv0 = 1.f / l0, inv1 = 1.f / l1;
    float* __restrict__ Og = g_O + (bh * SQ + q0) * DH;
    #pragma unroll
    for (int nt = 0; nt < 12; nt++) {
        int d0 = nt*8 + 2*tig;
        *(float2*)&Og[r0l*DH + d0] = make_float2(o[nt][0]*inv0, o[nt][1]*inv0);
        *(float2*)&Og[r1l*DH + d0] = make_float2(o[nt][2]*inv1, o[nt][3]*inv1);
    }
}

// ---------------------------------------------------------------------------
extern "C" void kernel_launch(void* const* d_in, const int* in_sizes, int n_in,
                              void* d_out, int out_size)
{
    const float* xq = (const float*)d_in[0];
    const float* xk = (const float*)d_in[1];
    const float* xv = (const float*)d_in[2];
    const float* Wq = (const float*)d_in[3];
    const float* bq = (const float*)d_in[4];
    const float* Wk = (const float*)d_in[5];
    const float* bk = (const float*)d_in[6];
    const float* Wv = (const float*)d_in[7];
    const float* bv = (const float*)d_in[8];
    const float* Wo = (const float*)d_in[9];
    const float* bo = (const float*)d_in[10];
    float* out = (float*)d_out;

    qkv_kernel<<<dim3(DM/128, M_TOT/128, 3), 128>>>(
        xq, xk, xv, Wq, Wk, Wv, bq, bk, bv);

    cudaFuncSetAttribute(attn_kernel,
                         cudaFuncAttributeMaxDynamicSharedMemorySize, ATTN_SMEM);
    attn_kernel<<<dim3(SQ/128, NB*NH), 256, ATTN_SMEM>>>();

    oproj_kernel<<<dim3(DM/128, M_TOT/128), 128>>>(Wo, bo, out);
}